// round 2
// baseline (speedup 1.0000x reference)
#include <cuda_runtime.h>
#include <math.h>

#define Bsz  128
#define Tlen 1024
#define Hd   256
#define NOUT 2

typedef unsigned long long u64;

// Scratch buffers (device globals — allocation is forbidden)
__device__ float g_bufA[Bsz * Tlen * Hd];  // pre-activations
__device__ float g_bufB[Bsz * Tlen * Hd];  // layer-1 hidden states

// ---------- packed fp32x2 FMA helpers (full-rate fp32 path on sm_103a) ------
__device__ __forceinline__ void fma2(u64& acc, u64 a, u64 b) {
    asm("fma.rn.f32x2 %0, %1, %2, %0;" : "+l"(acc) : "l"(a), "l"(b));
}
__device__ __forceinline__ u64 dup2(float x) {
    u64 r; asm("mov.b64 %0, {%1, %1};" : "=l"(r) : "f"(x)); return r;
}
__device__ __forceinline__ float2 unpk(u64 v) {
    float2 r; asm("mov.b64 {%0, %1}, %2;" : "=f"(r.x), "=f"(r.y) : "l"(v)); return r;
}

// =============================================================================
// GEMM: out[m][n] = sum_k A[m][k]*W[n][k] + bias[n];  M=131072, N=K=256.
// Tile 128(m) x 128(n), 256 threads, K staged in 4 chunks of 64.
// =============================================================================
#define WS_STRIDE 130
#define AS_STRIDE 129
#define GEMM_SMEM ((Hd * WS_STRIDE + 64 * AS_STRIDE) * 4)

__global__ void __launch_bounds__(256, 1) gemm_kernel(
    const float* __restrict__ A, const float* __restrict__ W,
    const float* __restrict__ bias, float* __restrict__ out)
{
    extern __shared__ float sm[];
    float* Ws = sm;                    // [K=256][130]  (k-major, n contiguous)
    float* As = sm + Hd * WS_STRIDE;   // [64][129]     (k-major, m contiguous)

    const int t   = threadIdx.x;
    const int nt  = blockIdx.x & 1;
    const int mt  = blockIdx.x >> 1;
    const int m0  = mt * 128, n0 = nt * 128;
    const int kq  = t & 15;          // float4 index along K
    const int rn  = t >> 4;          // row group 0..15
    const int ml  = t & 15;          // per-thread m base (m = ml + 16*i)
    const int tn2 = (t >> 4) << 1;   // per-thread n-pair base (n = tn2 + 32*j)

    // Load full-K W tile, transposed into Ws[k][n]
    const float4* W4 = (const float4*)(W + (size_t)n0 * Hd);
    #pragma unroll
    for (int p = 0; p < 8; ++p) {
        int row = rn + (p << 4);                 // n-local
        #pragma unroll
        for (int q = 0; q < 4; ++q) {
            float4 v = W4[row * 64 + (q << 4) + kq];
            int k = (((q << 4) + kq) << 2);
            Ws[(k + 0) * WS_STRIDE + row] = v.x;
            Ws[(k + 1) * WS_STRIDE + row] = v.y;
            Ws[(k + 2) * WS_STRIDE + row] = v.z;
            Ws[(k + 3) * WS_STRIDE + row] = v.w;
        }
    }

    u64 acc[8][4];
    #pragma unroll
    for (int i = 0; i < 8; ++i)
        #pragma unroll
        for (int j = 0; j < 4; ++j) acc[i][j] = 0ull;

    const float4* A4 = (const float4*)(A + (size_t)m0 * Hd);

    for (int s = 0; s < 4; ++s) {
        __syncthreads();
        #pragma unroll
        for (int p = 0; p < 8; ++p) {
            int row = rn + (p << 4);             // m-local
            float4 v = A4[row * 64 + (s << 4) + kq];
            int k = kq << 2;
            As[(k + 0) * AS_STRIDE + row] = v.x;
            As[(k + 1) * AS_STRIDE + row] = v.y;
            As[(k + 2) * AS_STRIDE + row] = v.z;
            As[(k + 3) * AS_STRIDE + row] = v.w;
        }
        __syncthreads();

        const int kbase = s << 6;
        #pragma unroll 4
        for (int kk = 0; kk < 64; ++kk) {
            u64 ad[8];
            #pragma unroll
            for (int i = 0; i < 8; ++i)
                ad[i] = dup2(As[kk * AS_STRIDE + ml + (i << 4)]);
            u64 bp[4];
            #pragma unroll
            for (int j = 0; j < 4; ++j)
                bp[j] = *(const u64*)&Ws[(kbase + kk) * WS_STRIDE + tn2 + (j << 5)];
            #pragma unroll
            for (int i = 0; i < 8; ++i)
                #pragma unroll
                for (int j = 0; j < 4; ++j)
                    fma2(acc[i][j], ad[i], bp[j]);
        }
    }

    #pragma unroll
    for (int j = 0; j < 4; ++j) {
        int n = n0 + tn2 + (j << 5);
        float bv0 = bias[n], bv1 = bias[n + 1];
        #pragma unroll
        for (int i = 0; i < 8; ++i) {
            int m = m0 + ml + (i << 4);
            float2 v = unpk(acc[i][j]);
            float2 r; r.x = v.x + bv0; r.y = v.y + bv1;
            *(float2*)&out[(size_t)m * Hd + n] = r;
        }
    }
}

// =============================================================================
// Recurrence: 1 CTA = 1 batch row. 512 threads: thread t -> output j = t&255,
// K-half kh = t>>8. W_hh row segment (128 w): 64 in regs + 64 in smem.
// h broadcast from smem; pre prefetched one step ahead.
// =============================================================================
#define RCH_REG 16   // float4 count in registers (64 floats)
#define RCH_SM  16   // float4 count in smem (64 floats)
#define REC_SMEM (512 * 4 + RCH_SM * 512 * 16)

template<bool WRITE_H, bool FINAL>
__global__ void __launch_bounds__(512, 1) recur_kernel(
    const float* __restrict__ pre, const float* __restrict__ Whh,
    float* __restrict__ hout,
    const float* __restrict__ fcw, const float* __restrict__ fcb,
    float* __restrict__ out)
{
    extern __shared__ float smf[];
    float* hcur = smf;                 // 256 floats
    float* part = smf + 256;           // 256 floats
    ulonglong2* Ws2 = (ulonglong2*)(smf + 512);  // [RCH_SM][512]

    const int t  = threadIdx.x;
    const int b  = blockIdx.x;
    const int j  = t & 255;
    const int kh = t >> 8;
    const int k0 = kh << 7;

    // Weights: 16 float4 -> registers, 16 float4 -> smem
    const ulonglong2* wg = (const ulonglong2*)(Whh + (size_t)j * Hd + k0);
    ulonglong2 wr[RCH_REG];
    #pragma unroll
    for (int c = 0; c < RCH_REG; ++c) wr[c] = wg[c];
    #pragma unroll
    for (int c = 0; c < RCH_SM; ++c) Ws2[c * 512 + t] = wg[RCH_REG + c];

    if (t < 256) hcur[t] = 0.f;
    const float* preb = pre + (size_t)b * Tlen * Hd;
    float p = (kh == 0) ? preb[j] : 0.f;
    __syncthreads();

    for (int step = 0; step < Tlen; ++step) {
        float p_next = 0.f;
        if (kh == 0) {
            int s2 = (step + 1 < Tlen) ? (step + 1) : step;
            p_next = preb[s2 * Hd + j];  // prefetch next pre-activation
        }

        const ulonglong2* h2 = (const ulonglong2*)(hcur + k0);
        u64 a0 = 0ull, a1 = 0ull, a2 = 0ull, a3 = 0ull;
        #pragma unroll
        for (int c = 0; c < RCH_REG; ++c) {
            ulonglong2 hv = h2[c];
            fma2(a0, wr[c].x, hv.x);
            fma2(a1, wr[c].y, hv.y);
        }
        #pragma unroll
        for (int c = 0; c < RCH_SM; ++c) {
            ulonglong2 hv = h2[RCH_REG + c];
            ulonglong2 wv = Ws2[c * 512 + t];
            fma2(a2, wv.x, hv.x);
            fma2(a3, wv.y, hv.y);
        }
        float2 s0 = unpk(a0), s1 = unpk(a1), s2v = unpk(a2), s3 = unpk(a3);
        float dot = (s0.x + s0.y) + (s1.x + s1.y) + (s2v.x + s2v.y) + (s3.x + s3.y);

        if (kh) part[j] = dot;
        __syncthreads();
        if (!kh) {
            float hn = tanhf(p + dot + part[j]);
            hcur[j] = hn;
            if (WRITE_H)
                hout[((size_t)b * Tlen + step) * Hd + j] = hn;
        }
        __syncthreads();
        p = p_next;
    }

    if (FINAL) {
        // out[b][o] = sum_j hcur[j]*fcw[o*256+j] + fcb[o], o in {0,1}
        if (t < 64) {
            int o = t >> 5, lane = t & 31;
            float s = 0.f;
            #pragma unroll
            for (int q = 0; q < 8; ++q)
                s += hcur[lane + (q << 5)] * fcw[o * Hd + lane + (q << 5)];
            #pragma unroll
            for (int off = 16; off; off >>= 1)
                s += __shfl_down_sync(0xffffffffu, s, off);
            if (lane == 0) out[b * NOUT + o] = s + fcb[o];
        }
    }
}

extern "C" void kernel_launch(void* const* d_in, const int* in_sizes, int n_in,
                              void* d_out, int out_size) {
    const float* x    = (const float*)d_in[0];
    const float* Wxh0 = (const float*)d_in[1];
    const float* Whh0 = (const float*)d_in[2];
    const float* b0   = (const float*)d_in[3];
    const float* Wxh1 = (const float*)d_in[4];
    const float* Whh1 = (const float*)d_in[5];
    const float* b1   = (const float*)d_in[6];
    const float* fcw  = (const float*)d_in[7];
    const float* fcb  = (const float*)d_in[8];
    float* out = (float*)d_out;

    float *bufA = nullptr, *bufB = nullptr;
    cudaGetSymbolAddress((void**)&bufA, g_bufA);
    cudaGetSymbolAddress((void**)&bufB, g_bufB);

    cudaFuncSetAttribute(gemm_kernel,
        cudaFuncAttributeMaxDynamicSharedMemorySize, GEMM_SMEM);
    cudaFuncSetAttribute(recur_kernel<true, false>,
        cudaFuncAttributeMaxDynamicSharedMemorySize, REC_SMEM);
    cudaFuncSetAttribute(recur_kernel<false, true>,
        cudaFuncAttributeMaxDynamicSharedMemorySize, REC_SMEM);

    // Layer 1: pre1 = x @ Wxh0^T + b0 ; h1 = scan(tanh)
    gemm_kernel<<<2048, 256, GEMM_SMEM>>>(x, Wxh0, b0, bufA);
    recur_kernel<true, false><<<Bsz, 512, REC_SMEM>>>(
        bufA, Whh0, bufB, nullptr, nullptr, nullptr);

    // Layer 2: pre2 = h1 @ Wxh1^T + b1 ; h2 = scan(tanh); head on last step
    gemm_kernel<<<2048, 256, GEMM_SMEM>>>(bufB, Wxh1, b1, bufA);
    recur_kernel<false, true><<<Bsz, 512, REC_SMEM>>>(
        bufA, Whh1, nullptr, fcw, fcb, out);
}

// round 3
// speedup vs baseline: 1.6161x; 1.6161x over previous
#include <cuda_runtime.h>
#include <math.h>

#define Bsz  128
#define Tlen 1024
#define Hd   256
#define NOUT 2

typedef unsigned long long u64;

// Scratch buffers (device globals — allocation is forbidden)
__device__ float g_bufA[Bsz * Tlen * Hd];  // pre-activations
__device__ float g_bufB[Bsz * Tlen * Hd];  // layer-1 hidden states

// ---------- packed fp32x2 helpers (full-rate fp32 path on sm_103a) ----------
__device__ __forceinline__ void fma2(u64& acc, u64 a, u64 b) {
    asm("fma.rn.f32x2 %0, %1, %2, %0;" : "+l"(acc) : "l"(a), "l"(b));
}
__device__ __forceinline__ u64 add2(u64 a, u64 b) {
    u64 r; asm("add.rn.f32x2 %0, %1, %2;" : "=l"(r) : "l"(a), "l"(b)); return r;
}
__device__ __forceinline__ u64 dup2(float x) {
    u64 r; asm("mov.b64 %0, {%1, %1};" : "=l"(r) : "f"(x)); return r;
}
__device__ __forceinline__ float2 unpk(u64 v) {
    float2 r; asm("mov.b64 {%0, %1}, %2;" : "=f"(r.x), "=f"(r.y) : "l"(v)); return r;
}

// =============================================================================
// GEMM (unchanged from R1 — known good): out = A @ W^T + bias
// M=131072, N=K=256. Tile 128x128, 256 threads, K staged in 4 chunks of 64.
// =============================================================================
#define WS_STRIDE 130
#define AS_STRIDE 129
#define GEMM_SMEM ((Hd * WS_STRIDE + 64 * AS_STRIDE) * 4)

__global__ void __launch_bounds__(256, 1) gemm_kernel(
    const float* __restrict__ A, const float* __restrict__ W,
    const float* __restrict__ bias, float* __restrict__ out)
{
    extern __shared__ float sm[];
    float* Ws = sm;                    // [K=256][130]
    float* As = sm + Hd * WS_STRIDE;   // [64][129]

    const int t   = threadIdx.x;
    const int nt  = blockIdx.x & 1;
    const int mt  = blockIdx.x >> 1;
    const int m0  = mt * 128, n0 = nt * 128;
    const int kq  = t & 15;
    const int rn  = t >> 4;
    const int ml  = t & 15;
    const int tn2 = (t >> 4) << 1;

    const float4* W4 = (const float4*)(W + (size_t)n0 * Hd);
    #pragma unroll
    for (int p = 0; p < 8; ++p) {
        int row = rn + (p << 4);
        #pragma unroll
        for (int q = 0; q < 4; ++q) {
            float4 v = W4[row * 64 + (q << 4) + kq];
            int k = (((q << 4) + kq) << 2);
            Ws[(k + 0) * WS_STRIDE + row] = v.x;
            Ws[(k + 1) * WS_STRIDE + row] = v.y;
            Ws[(k + 2) * WS_STRIDE + row] = v.z;
            Ws[(k + 3) * WS_STRIDE + row] = v.w;
        }
    }

    u64 acc[8][4];
    #pragma unroll
    for (int i = 0; i < 8; ++i)
        #pragma unroll
        for (int j = 0; j < 4; ++j) acc[i][j] = 0ull;

    const float4* A4 = (const float4*)(A + (size_t)m0 * Hd);

    for (int s = 0; s < 4; ++s) {
        __syncthreads();
        #pragma unroll
        for (int p = 0; p < 8; ++p) {
            int row = rn + (p << 4);
            float4 v = A4[row * 64 + (s << 4) + kq];
            int k = kq << 2;
            As[(k + 0) * AS_STRIDE + row] = v.x;
            As[(k + 1) * AS_STRIDE + row] = v.y;
            As[(k + 2) * AS_STRIDE + row] = v.z;
            As[(k + 3) * AS_STRIDE + row] = v.w;
        }
        __syncthreads();

        const int kbase = s << 6;
        #pragma unroll 4
        for (int kk = 0; kk < 64; ++kk) {
            u64 ad[8];
            #pragma unroll
            for (int i = 0; i < 8; ++i)
                ad[i] = dup2(As[kk * AS_STRIDE + ml + (i << 4)]);
            u64 bp[4];
            #pragma unroll
            for (int j = 0; j < 4; ++j)
                bp[j] = *(const u64*)&Ws[(kbase + kk) * WS_STRIDE + tn2 + (j << 5)];
            #pragma unroll
            for (int i = 0; i < 8; ++i)
                #pragma unroll
                for (int j = 0; j < 4; ++j)
                    fma2(acc[i][j], ad[i], bp[j]);
        }
    }

    #pragma unroll
    for (int j = 0; j < 4; ++j) {
        int n = n0 + tn2 + (j << 5);
        float bv0 = bias[n], bv1 = bias[n + 1];
        #pragma unroll
        for (int i = 0; i < 8; ++i) {
            int m = m0 + ml + (i << 4);
            float2 v = unpk(acc[i][j]);
            float2 r; r.x = v.x + bv0; r.y = v.y + bv1;
            *(float2*)&out[(size_t)m * Hd + n] = r;
        }
    }
}

// =============================================================================
// Recurrence v2: 1 CTA = 1 batch row, 512 threads.
// Thread t -> output j = t>>1, K-half kh = t&1 (pair in same warp -> shfl_xor
// reduce, no smem round-trip). Ping-pong h buffers -> ONE barrier per step.
// Weights/thread = 128 floats: 80 in registers + 48 in smem.
// h half-stride padded to 132 floats so the 2-address broadcast loads are
// single-phase on the crossbar.
// =============================================================================
#define RREG 20   // float4 (ulonglong2) kept in registers (80 floats)
#define RSM  12   // float4 kept in smem (48 floats)
#define HSTR 132            // padded half-stride (floats)
#define HBUF (2 * 2 * HSTR) // 2 parities x 2 halves = 528 floats
#define REC_SMEM (HBUF * 4 + RSM * 512 * 16)

__device__ __forceinline__ float fast_tanh(float x) {
    // tanh(x) = 1 - 2/(e^{2x}+1); MUFU-based, correct saturation at +-inf.
    float e = __expf(2.0f * x);
    return 1.0f - 2.0f * __fdividef(1.0f, e + 1.0f);
}

template<bool WRITE_H, bool FINAL>
__global__ void __launch_bounds__(512, 1) recur_kernel(
    const float* __restrict__ pre, const float* __restrict__ Whh,
    float* __restrict__ hout,
    const float* __restrict__ fcw, const float* __restrict__ fcb,
    float* __restrict__ out)
{
    extern __shared__ float smf[];
    float* hbuf = smf;                                   // [2][2*HSTR]
    ulonglong2* Wsm = (ulonglong2*)(smf + HBUF);         // [RSM][512]

    const int t  = threadIdx.x;
    const int b  = blockIdx.x;
    const int j  = t >> 1;
    const int kh = t & 1;

    // Load this thread's 128 weights: 20 f4 -> regs, 12 f4 -> smem
    const ulonglong2* wg =
        (const ulonglong2*)(Whh + (size_t)j * Hd + (kh << 7));
    ulonglong2 wr[RREG];
    #pragma unroll
    for (int c = 0; c < RREG; ++c) wr[c] = wg[c];
    #pragma unroll
    for (int c = 0; c < RSM; ++c) Wsm[c * 512 + t] = wg[RREG + c];

    if (t < HBUF) hbuf[t] = 0.f;   // zero both parities (h0 = 0)

    const float* preb = pre + (size_t)b * Tlen * Hd;
    float p = preb[j];             // pre-activation for step 0
    const int wslot = j + ((j >> 7) << 2);   // padded write index
    __syncthreads();

    for (int step = 0; step < Tlen; ++step) {
        // prefetch next step's pre-activation (slack ~1 full step)
        int sn = (step + 1 < Tlen) ? step + 1 : step;
        float pn = preb[sn * Hd + j];

        const ulonglong2* h2 =
            (const ulonglong2*)(hbuf + (step & 1) * (2 * HSTR) + kh * HSTR);

        u64 a0 = 0ull, a1 = 0ull, a2 = 0ull, a3 = 0ull;
        #pragma unroll
        for (int c = 0; c < RSM; ++c) {
            ulonglong2 hv = h2[RREG + c];
            ulonglong2 wv = Wsm[c * 512 + t];
            fma2(a2, wv.x, hv.x);
            fma2(a3, wv.y, hv.y);
        }
        #pragma unroll
        for (int c = 0; c < RREG; ++c) {
            ulonglong2 hv = h2[c];
            fma2(a0, wr[c].x, hv.x);
            fma2(a1, wr[c].y, hv.y);
        }

        u64 s01 = add2(add2(a0, a1), add2(a2, a3));
        float2 f = unpk(s01);
        float d = f.x + f.y;
        d += __shfl_xor_sync(0xffffffffu, d, 1);   // fold the two K-halves

        float hn = fast_tanh(p + d);

        if (kh == 0) {
            hbuf[((step + 1) & 1) * (2 * HSTR) + wslot] = hn;
            if (WRITE_H)
                hout[((size_t)b * Tlen + step) * Hd + j] = hn;
        }
        __syncthreads();
        p = pn;
    }

    if (FINAL) {
        // final h lives in parity (Tlen & 1) == 0
        if (t < 64) {
            int o = t >> 5, lane = t & 31;
            float s = 0.f;
            #pragma unroll
            for (int q = 0; q < 8; ++q) {
                int jj = lane + (q << 5);
                s += hbuf[jj + ((jj >> 7) << 2)] * fcw[o * Hd + jj];
            }
            #pragma unroll
            for (int off = 16; off; off >>= 1)
                s += __shfl_down_sync(0xffffffffu, s, off);
            if (lane == 0) out[b * NOUT + o] = s + fcb[o];
        }
    }
}

extern "C" void kernel_launch(void* const* d_in, const int* in_sizes, int n_in,
                              void* d_out, int out_size) {
    const float* x    = (const float*)d_in[0];
    const float* Wxh0 = (const float*)d_in[1];
    const float* Whh0 = (const float*)d_in[2];
    const float* b0   = (const float*)d_in[3];
    const float* Wxh1 = (const float*)d_in[4];
    const float* Whh1 = (const float*)d_in[5];
    const float* b1   = (const float*)d_in[6];
    const float* fcw  = (const float*)d_in[7];
    const float* fcb  = (const float*)d_in[8];
    float* out = (float*)d_out;

    float *bufA = nullptr, *bufB = nullptr;
    cudaGetSymbolAddress((void**)&bufA, g_bufA);
    cudaGetSymbolAddress((void**)&bufB, g_bufB);

    cudaFuncSetAttribute(gemm_kernel,
        cudaFuncAttributeMaxDynamicSharedMemorySize, GEMM_SMEM);
    cudaFuncSetAttribute(recur_kernel<true, false>,
        cudaFuncAttributeMaxDynamicSharedMemorySize, REC_SMEM);
    cudaFuncSetAttribute(recur_kernel<false, true>,
        cudaFuncAttributeMaxDynamicSharedMemorySize, REC_SMEM);

    // Layer 1
    gemm_kernel<<<2048, 256, GEMM_SMEM>>>(x, Wxh0, b0, bufA);
    recur_kernel<true, false><<<Bsz, 512, REC_SMEM>>>(
        bufA, Whh0, bufB, nullptr, nullptr, nullptr);

    // Layer 2 + head
    gemm_kernel<<<2048, 256, GEMM_SMEM>>>(bufB, Wxh1, b1, bufA);
    recur_kernel<false, true><<<Bsz, 512, REC_SMEM>>>(
        bufA, Whh1, nullptr, fcw, fcb, out);
}